// round 17
// baseline (speedup 1.0000x reference)
#include <cuda_runtime.h>
#include <math.h>

#define NN 50000

// ---------------- scratch (static device globals) ----------------
__device__ float g_W1f[384 * 512];             // [W1l | W1r] fused
__device__ float g_W2f[256 * 256];             // [W2l | W2r] fused
__device__ float g_y1[(size_t)NN * 512];       // [xcat@W1l | xcat@W1r]
__device__ float g_agg1[(size_t)NN * 256];     // edge-agg of y1l
__device__ float g_cnt[NN];                    // in-degree
__device__ float g_h1[(size_t)NN * 256];       // relu SAGE1 out
__device__ float g_y2[(size_t)NN * 256];       // [h1@W2l | h1@W2r]
__device__ float g_agg2[(size_t)NN * 128];
__device__ float g_hg[(size_t)NN * 128];       // normalized h_g
__device__ float g_hidden[(size_t)NN * 256];   // classifier hidden
__device__ int   g_idx64;                      // 1 if edge_index is int64-layout

// ---------------- index dtype detection ----------------
__global__ void k_detect_idx(const int* __restrict__ e, int nPairsToCheck) {
    if (blockIdx.x == 0 && threadIdx.x == 0) {
        int is64 = 1;
        for (int i = 0; i < nPairsToCheck; i++) {
            if (e[2 * i + 1] != 0) { is64 = 0; break; }
        }
        g_idx64 = is64;
    }
}

// ---------------- utility kernels ----------------
__global__ void k_zero_scratch(int n) {
    size_t n0 = (size_t)n * 256;
    size_t n1 = (size_t)n * 128;
    size_t n2 = (size_t)n;
    size_t total = n0 + n1 + n2;
    size_t i = (size_t)blockIdx.x * blockDim.x + threadIdx.x;
    size_t stride = (size_t)gridDim.x * blockDim.x;
    for (; i < total; i += stride) {
        if (i < n0) g_agg1[i] = 0.f;
        else if (i < n0 + n1) g_agg2[i - n0] = 0.f;
        else g_cnt[i - n0 - n1] = 0.f;
    }
}

__global__ void k_fuseW1(const float* __restrict__ Wl, const float* __restrict__ Wr) {
    int i = blockIdx.x * blockDim.x + threadIdx.x;
    int total = 384 * 256;
    int stride = gridDim.x * blockDim.x;
    for (; i < total; i += stride) {
        int k = i >> 8, j = i & 255;
        g_W1f[(size_t)k * 512 + j] = Wl[i];
        g_W1f[(size_t)k * 512 + 256 + j] = Wr[i];
    }
}

__global__ void k_fuseW2(const float* __restrict__ Wl, const float* __restrict__ Wr) {
    int i = blockIdx.x * blockDim.x + threadIdx.x;
    int total = 256 * 128;
    int stride = gridDim.x * blockDim.x;
    for (; i < total; i += stride) {
        int k = i >> 7, j = i & 127;
        g_W2f[(size_t)k * 256 + j] = Wl[i];
        g_W2f[(size_t)k * 256 + 128 + j] = Wr[i];
    }
}

// ---------------- 3xTF32 split-precision GEMM ----------------
// C[M,Nc] = A[M,K] @ B[K,Nc] (+bias)(+relu), fp32-accurate via hi/lo TF32 split.
// Block tile 128x64, BK=16, 256 threads = 8 warps, warp tile 32x32.
// NSEG>1: A = virtual concat [A0|A1|A2|A3], segments of 128 cols.

__device__ __forceinline__ void split_tf32(float x, unsigned& hi, unsigned& lo) {
    unsigned xb = __float_as_uint(x);
    unsigned h = xb & 0xFFFFE000u;
    hi = h;
    lo = __float_as_uint(x - __uint_as_float(h));
}

__device__ __forceinline__ void mma1688(float* c, unsigned a0, unsigned a1,
                                        unsigned a2, unsigned a3,
                                        unsigned b0, unsigned b1) {
    asm volatile(
        "mma.sync.aligned.m16n8k8.row.col.f32.tf32.tf32.f32 "
        "{%0,%1,%2,%3}, {%4,%5,%6,%7}, {%8,%9}, {%0,%1,%2,%3};"
        : "+f"(c[0]), "+f"(c[1]), "+f"(c[2]), "+f"(c[3])
        : "r"(a0), "r"(a1), "r"(a2), "r"(a3), "r"(b0), "r"(b1));
}

#define A_STRIDE 20   // 16 k + pad 4  -> frag loads conflict-free
#define B_STRIDE 72   // 64 n + pad 8  -> (8k+n)%32 distinct

template <bool RELU, int NSEG>
__device__ __forceinline__ void tf32_gemm_body(
        const float* __restrict__ A0, const float* __restrict__ A1,
        const float* __restrict__ A2, const float* __restrict__ A3, int lda,
        const float* __restrict__ B,
        const float* __restrict__ bias,
        float* __restrict__ C, int ldc,
        int M, int K, int Nc, int tileX, int tileY) {
    __shared__ float Ahi[128][A_STRIDE];
    __shared__ float Alo[128][A_STRIDE];
    __shared__ float Bhi[16][B_STRIDE];
    __shared__ float Blo[16][B_STRIDE];

    const int tid = threadIdx.x;
    const int wid = tid >> 5;
    const int lane = tid & 31;
    const int qr = lane >> 2;       // 0..7
    const int qc = lane & 3;        // 0..3
    const int wm = (wid & 3) * 32;  // warp row base in tile
    const int wn = (wid >> 2) * 32; // warp col base in tile
    const int rowBase = tileY * 128;
    const int colBase = tileX * 64;

    // A loader: row per thread-pair
    const int aRow = tid >> 1;            // 0..127
    const int aCol = (tid & 1) * 8;       // 0 or 8
    const int aGrRaw = rowBase + aRow;
    const bool aOk = (aGrRaw < M);
    const int aGr = aOk ? aGrRaw : 0;

    // B loader: 16x64 floats -> 4 per thread
    const int bRow = tid >> 4;            // 0..15
    const int bCol = (tid & 15) * 4;      // 0..60
    const float* bPtr = B + (size_t)bRow * Nc + colBase + bCol;

    float acc[2][4][4];
#pragma unroll
    for (int i = 0; i < 2; i++)
#pragma unroll
        for (int j = 0; j < 4; j++)
#pragma unroll
            for (int q = 0; q < 4; q++) acc[i][j][q] = 0.f;

    float pa[8];
    float pb[4];

    auto loadA = [&](int kk) {
        const float* ap;
        if (NSEG > 1) {
            int col = kk + aCol;
            int seg = col >> 7;
            int off = col & 127;
            const float* base = A0;
            if (NSEG >= 2 && seg == 1) base = A1;
            if (NSEG >= 3 && seg == 2) base = A2;
            if (NSEG >= 4 && seg == 3) base = A3;
            ap = base + (size_t)aGr * 128 + off;
        } else {
            ap = A0 + (size_t)aGr * lda + kk + aCol;
        }
        if (aOk) {
            float4 v0 = *reinterpret_cast<const float4*>(ap);
            float4 v1 = *reinterpret_cast<const float4*>(ap + 4);
            pa[0] = v0.x; pa[1] = v0.y; pa[2] = v0.z; pa[3] = v0.w;
            pa[4] = v1.x; pa[5] = v1.y; pa[6] = v1.z; pa[7] = v1.w;
        } else {
#pragma unroll
            for (int i = 0; i < 8; i++) pa[i] = 0.f;
        }
    };
    auto loadB = [&](int kk) {
        float4 v = *reinterpret_cast<const float4*>(bPtr + (size_t)kk * Nc);
        pb[0] = v.x; pb[1] = v.y; pb[2] = v.z; pb[3] = v.w;
    };
    auto storeTile = [&]() {
#pragma unroll
        for (int i = 0; i < 8; i++) {
            unsigned h, l;
            split_tf32(pa[i], h, l);
            Ahi[aRow][aCol + i] = __uint_as_float(h);
            Alo[aRow][aCol + i] = __uint_as_float(l);
        }
#pragma unroll
        for (int i = 0; i < 4; i++) {
            unsigned h, l;
            split_tf32(pb[i], h, l);
            Bhi[bRow][bCol + i] = __uint_as_float(h);
            Blo[bRow][bCol + i] = __uint_as_float(l);
        }
    };

    loadA(0);
    loadB(0);

    for (int kk = 0; kk < K; kk += 16) {
        __syncthreads();          // previous compute done
        storeTile();
        __syncthreads();          // tile visible
        const bool hasNext = (kk + 16) < K;
        if (hasNext) {            // prefetch next (overlaps compute below)
            loadA(kk + 16);
            loadB(kk + 16);
        }
#pragma unroll
        for (int kb = 0; kb < 16; kb += 8) {
            // load fragments
            unsigned ah[2][4], al[2][4];
#pragma unroll
            for (int mt = 0; mt < 2; mt++) {
                int r0 = wm + mt * 16 + qr;
                int r1 = r0 + 8;
                int c0 = kb + qc;
                ah[mt][0] = __float_as_uint(Ahi[r0][c0]);
                ah[mt][1] = __float_as_uint(Ahi[r1][c0]);
                ah[mt][2] = __float_as_uint(Ahi[r0][c0 + 4]);
                ah[mt][3] = __float_as_uint(Ahi[r1][c0 + 4]);
                al[mt][0] = __float_as_uint(Alo[r0][c0]);
                al[mt][1] = __float_as_uint(Alo[r1][c0]);
                al[mt][2] = __float_as_uint(Alo[r0][c0 + 4]);
                al[mt][3] = __float_as_uint(Alo[r1][c0 + 4]);
            }
            unsigned bh[4][2], bl[4][2];
#pragma unroll
            for (int nt = 0; nt < 4; nt++) {
                int n = wn + nt * 8 + qr;
                bh[nt][0] = __float_as_uint(Bhi[kb + qc][n]);
                bh[nt][1] = __float_as_uint(Bhi[kb + qc + 4][n]);
                bl[nt][0] = __float_as_uint(Blo[kb + qc][n]);
                bl[nt][1] = __float_as_uint(Blo[kb + qc + 4][n]);
            }
#pragma unroll
            for (int mt = 0; mt < 2; mt++)
#pragma unroll
                for (int nt = 0; nt < 4; nt++) {
                    float* c = acc[mt][nt];
                    mma1688(c, ah[mt][0], ah[mt][1], ah[mt][2], ah[mt][3],
                            bh[nt][0], bh[nt][1]);
                    mma1688(c, ah[mt][0], ah[mt][1], ah[mt][2], ah[mt][3],
                            bl[nt][0], bl[nt][1]);
                    mma1688(c, al[mt][0], al[mt][1], al[mt][2], al[mt][3],
                            bh[nt][0], bh[nt][1]);
                }
        }
    }

    // epilogue
#pragma unroll
    for (int mt = 0; mt < 2; mt++)
#pragma unroll
        for (int nt = 0; nt < 4; nt++) {
            int col = colBase + wn + nt * 8 + 2 * qc;
            float b0 = 0.f, b1 = 0.f;
            if (bias) { b0 = bias[col]; b1 = bias[col + 1]; }
            int r0 = rowBase + wm + mt * 16 + qr;
            int r1 = r0 + 8;
            float v0 = acc[mt][nt][0] + b0;
            float v1 = acc[mt][nt][1] + b1;
            float v2 = acc[mt][nt][2] + b0;
            float v3 = acc[mt][nt][3] + b1;
            if (RELU) {
                v0 = fmaxf(v0, 0.f); v1 = fmaxf(v1, 0.f);
                v2 = fmaxf(v2, 0.f); v3 = fmaxf(v3, 0.f);
            }
            if (r0 < M) {
                float2 p = make_float2(v0, v1);
                *reinterpret_cast<float2*>(C + (size_t)r0 * ldc + col) = p;
            }
            if (r1 < M) {
                float2 p = make_float2(v2, v3);
                *reinterpret_cast<float2*>(C + (size_t)r1 * ldc + col) = p;
            }
        }
}

// layer 1: [h_v|h_t|h_tab] @ g_W1f -> g_y1 [N,512]
__global__ void __launch_bounds__(256, 2)
k_l1gemm(const float* __restrict__ h_v, const float* __restrict__ h_t,
         const float* __restrict__ h_tab, int M) {
    tf32_gemm_body<false, 3>(h_v, h_t, h_tab, nullptr, 0, g_W1f, nullptr,
                             g_y1, 512, M, 384, 512, blockIdx.x, blockIdx.y);
}

// layer 2: g_h1 @ g_W2f -> g_y2 [N,256]
__global__ void __launch_bounds__(256, 2)
k_l2gemm(int M) {
    tf32_gemm_body<false, 1>(g_h1, nullptr, nullptr, nullptr, 256, g_W2f, nullptr,
                             g_y2, 256, M, 256, 256, blockIdx.x, blockIdx.y);
}

// projections: z selects (A, B, bias); writes contiguous z regions of d_out.
__global__ void __launch_bounds__(256, 2)
k_proj3(const float* __restrict__ Aht, const float* __restrict__ Ahtab,
        const float* __restrict__ Wsh, const float* __restrict__ bsh,
        const float* __restrict__ Wst, const float* __restrict__ bst,
        const float* __restrict__ Wstab, const float* __restrict__ bstab,
        float* __restrict__ zout, int M) {
    const float* A;
    const float* B;
    const float* bias;
    int z = blockIdx.z;
    if (z == 0)      { A = g_hg;  B = Wsh;   bias = bsh;   }
    else if (z == 1) { A = Aht;   B = Wst;   bias = bst;   }
    else             { A = Ahtab; B = Wstab; bias = bstab; }
    float* C = zout + (size_t)z * M * 128;
    tf32_gemm_body<false, 1>(A, nullptr, nullptr, nullptr, 128, B, bias,
                             C, 128, M, 128, 128, blockIdx.x, blockIdx.y);
}

// classifier: [z_shared|z_t|z_tab|g_hg] @ Wc1 + bc1, relu -> g_hidden [N,256]
__global__ void __launch_bounds__(256, 2)
k_clsgemm(const float* __restrict__ zout,
          const float* __restrict__ Wc1, const float* __restrict__ bc1, int M) {
    tf32_gemm_body<true, 4>(zout, zout + (size_t)M * 128, zout + (size_t)M * 256,
                            g_hg, 0, Wc1, bc1, g_hidden, 256,
                            M, 512, 256, blockIdx.x, blockIdx.y);
}

// ---------------- edge kernels ----------------
template <bool LAYER1>
__global__ void k_edge_agg(const void* __restrict__ eidx, int E, int N) {
    const int is64 = g_idx64;
    int gwarp = (blockIdx.x * blockDim.x + threadIdx.x) >> 5;
    int lane = threadIdx.x & 31;
    int nWarps = (gridDim.x * blockDim.x) >> 5;
    const long long* e64 = (const long long*)eidx;
    const int* e32 = (const int*)eidx;
    for (int e = gwarp; e < E; e += nWarps) {
        int s, d;
        if (is64) {
            s = (int)e64[e];
            d = (int)e64[E + e];
        } else {
            s = e32[e];
            d = e32[E + e];
        }
        if ((unsigned)s >= (unsigned)N || (unsigned)d >= (unsigned)N) continue;
        if (LAYER1) {
            if (lane == 0) atomicAdd(&g_cnt[d], 1.0f);
            const float4* xs = reinterpret_cast<const float4*>(&g_y1[(size_t)s * 512]);
            float* ad = &g_agg1[(size_t)d * 256];
#pragma unroll
            for (int p = lane; p < 64; p += 32) {
                float4 v = xs[p];
                atomicAdd(ad + p * 4 + 0, v.x);
                atomicAdd(ad + p * 4 + 1, v.y);
                atomicAdd(ad + p * 4 + 2, v.z);
                atomicAdd(ad + p * 4 + 3, v.w);
            }
        } else {
            const float4* xs = reinterpret_cast<const float4*>(&g_y2[(size_t)s * 256]);
            float* ad = &g_agg2[(size_t)d * 128];
            float4 v = xs[lane];
            atomicAdd(ad + lane * 4 + 0, v.x);
            atomicAdd(ad + lane * 4 + 1, v.y);
            atomicAdd(ad + lane * 4 + 2, v.z);
            atomicAdd(ad + lane * 4 + 3, v.w);
        }
    }
}

// g_h1 = relu(g_agg1/max(cnt,1) + b1g + g_y1[:,256:512])
__global__ void k_combine1(const float* __restrict__ b1g, int n) {
    size_t idx = (size_t)blockIdx.x * blockDim.x + threadIdx.x;
    size_t total = (size_t)n * 64;
    size_t stride = (size_t)gridDim.x * blockDim.x;
    for (; idx < total; idx += stride) {
        int row = (int)(idx >> 6);
        int j4 = (int)(idx & 63);
        float inv = 1.0f / fmaxf(g_cnt[row], 1.0f);
        float4 a = reinterpret_cast<const float4*>(g_agg1)[idx];
        float4 y = reinterpret_cast<const float4*>(g_y1)[(size_t)row * 128 + 64 + j4];
        float4 b = reinterpret_cast<const float4*>(b1g)[j4];
        float4 o;
        o.x = fmaxf(a.x * inv + b.x + y.x, 0.f);
        o.y = fmaxf(a.y * inv + b.y + y.y, 0.f);
        o.z = fmaxf(a.z * inv + b.z + y.z, 0.f);
        o.w = fmaxf(a.w * inv + b.w + y.w, 0.f);
        reinterpret_cast<float4*>(g_h1)[idx] = o;
    }
}

// g_hg row = normalize(g_agg2/max(cnt,1) + b2g + g_y2[:,128:256]); warp per row
__global__ void k_combine2_norm(const float* __restrict__ b2g, int n) {
    int warpId = (blockIdx.x * blockDim.x + threadIdx.x) >> 5;
    int lane = threadIdx.x & 31;
    if (warpId >= n) return;
    int row = warpId;
    float inv = 1.0f / fmaxf(g_cnt[row], 1.0f);
    float v[4];
    float s = 0.f;
#pragma unroll
    for (int q = 0; q < 4; q++) {
        int c = lane + q * 32;
        v[q] = g_agg2[(size_t)row * 128 + c] * inv + b2g[c]
             + g_y2[(size_t)row * 256 + 128 + c];
        s = fmaf(v[q], v[q], s);
    }
#pragma unroll
    for (int o = 16; o > 0; o >>= 1) s += __shfl_xor_sync(0xffffffffu, s, o);
    float scale = 1.0f / fmaxf(sqrtf(s), 1e-12f);
#pragma unroll
    for (int q = 0; q < 4; q++) {
        g_hg[(size_t)row * 128 + lane + q * 32] = v[q] * scale;
    }
}

// logits = g_hidden @ Wc2 + bc2   (K=256, Nc=14)
__global__ void k_logits(const float* __restrict__ Wc2, const float* __restrict__ bc2,
                         float* __restrict__ out, int n) {
    __shared__ float Ws[256 * 14];
    __shared__ float Hs[8][256];
    int tid = threadIdx.x;
    for (int i = tid; i < 256 * 14; i += 128) Ws[i] = Wc2[i];
    int rowBase = blockIdx.x * 8;
    for (int i = tid; i < 8 * 256; i += 128) {
        int r = i >> 8;
        int k = i & 255;
        int gr = rowBase + r;
        Hs[r][k] = (gr < n) ? g_hidden[(size_t)gr * 256 + k] : 0.f;
    }
    __syncthreads();
    if (tid < 112) {
        int r = tid / 14;
        int c = tid % 14;
        int gr = rowBase + r;
        if (gr < n) {
            float sum = 0.f;
#pragma unroll 8
            for (int k = 0; k < 256; k++) sum = fmaf(Hs[r][k], Ws[k * 14 + c], sum);
            out[(size_t)gr * 14 + c] = sum + bc2[c];
        }
    }
}

// ---------------- launch ----------------
extern "C" void kernel_launch(void* const* d_in, const int* in_sizes, int n_in,
                              void* d_out, int out_size) {
    const float* h_v   = (const float*)d_in[0];
    const float* h_t   = (const float*)d_in[1];
    const float* h_tab = (const float*)d_in[2];
    const void*  eidx  = d_in[3];
    const float* W1l = (const float*)d_in[4];
    const float* W1r = (const float*)d_in[5];
    const float* b1g = (const float*)d_in[6];
    const float* W2l = (const float*)d_in[7];
    const float* W2r = (const float*)d_in[8];
    const float* b2g = (const float*)d_in[9];
    const float* Wsh = (const float*)d_in[10];
    const float* bsh = (const float*)d_in[11];
    const float* Wst = (const float*)d_in[12];
    const float* bst = (const float*)d_in[13];
    const float* Wstab = (const float*)d_in[14];
    const float* bstab = (const float*)d_in[15];
    const float* Wc1 = (const float*)d_in[16];
    const float* bc1 = (const float*)d_in[17];
    const float* Wc2 = (const float*)d_in[18];
    const float* bc2 = (const float*)d_in[19];
    float* out = (float*)d_out;

    const int N = in_sizes[0] / 128;
    const int E = in_sizes[3] / 2;

    float* zout = out + (size_t)N * 14;

    k_detect_idx<<<1, 1>>>((const int*)eidx, 256);
    k_zero_scratch<<<4096, 256>>>(N);
    k_fuseW1<<<256, 256>>>(W1l, W1r);
    k_fuseW2<<<128, 256>>>(W2l, W2r);

    dim3 blk(256);
    int mTiles = (N + 127) / 128;

    // layer 1 fused GEMM (tf32x3): Nc=512 -> 8 col tiles
    k_l1gemm<<<dim3(8, mTiles), blk>>>(h_v, h_t, h_tab, N);

    k_edge_agg<true><<<16384, 256>>>(eidx, E, N);
    k_combine1<<<4096, 256>>>(b1g, N);

    // layer 2 fused GEMM: Nc=256 -> 4 col tiles
    k_l2gemm<<<dim3(4, mTiles), blk>>>(N);

    k_edge_agg<false><<<16384, 256>>>(eidx, E, N);
    k_combine2_norm<<<(N * 32 + 255) / 256, 256>>>(b2g, N);

    // projections: Nc=128 -> 2 col tiles, z = 3
    k_proj3<<<dim3(2, mTiles, 3), blk>>>(h_t, h_tab,
                                         Wsh, bsh, Wst, bst, Wstab, bstab,
                                         zout, N);

    // classifier: Nc=256 -> 4 col tiles
    k_clsgemm<<<dim3(4, mTiles), blk>>>(zout, Wc1, bc1, N);

    k_logits<<<(N + 7) / 8, 128>>>(Wc2, bc2, out, N);
}